// round 16
// baseline (speedup 1.0000x reference)
#include <cuda_runtime.h>
#include <cuda_fp16.h>
#include <cstdint>

#define TOK   4096
#define DIMN  512
#define GQ    32
#define HD    16
#define RNUM  4
#define INTER 405
#define INTP  408
#define DIN1  144
#define H1LD  576
#define HSLDP 1632
#define NSEQ  512

// ---------------- device scratch (fp16 payloads) ----------------
__device__ __half g_xc[TOK * DIMN];
__device__ __half g_wqt[DIMN * DIMN];     // [n][k]
__device__ __half g_wkt[DIMN * DIMN];
__device__ __half g_wvt[DIMN * DIMN];
__device__ __half g_wint[64 * DIMN];
__device__ __half g_w1t[RNUM * INTP * DIN1];   // per rule [408][144]
__device__ __half g_w2t[DIMN * HSLDP];         // [512][1632], pad k zero
__device__ __half g_qkv[3 * TOK * DIMN];
__device__ __half g_h1[TOK * H1LD];
__device__ __half g_hs[TOK * HSLDP];

// ---------------- helpers ----------------
__device__ __forceinline__ uint32_t smem_u32(const void* p) {
    uint32_t a;
    asm("{ .reg .u64 t; cvta.to.shared.u64 t, %1; cvt.u32.u64 %0, t; }"
        : "=r"(a) : "l"(p));
    return a;
}
__device__ __forceinline__ void cp16(uint32_t dst, const void* src, bool pred) {
    int sz = pred ? 16 : 0;
    asm volatile("cp.async.ca.shared.global [%0], [%1], 16, %2;"
                 :: "r"(dst), "l"(src), "r"(sz) : "memory");
}
#define CP_COMMIT() asm volatile("cp.async.commit_group;" ::: "memory")
#define CP_WAIT1()  asm volatile("cp.async.wait_group 1;" ::: "memory")
#define CP_WAIT0()  asm volatile("cp.async.wait_group 0;" ::: "memory")

__device__ __forceinline__ void mma_f16(float d[4], const uint32_t a[4],
                                        const uint32_t b[2]) {
    asm volatile(
        "mma.sync.aligned.m16n8k16.row.col.f32.f16.f16.f32 "
        "{%0,%1,%2,%3}, {%4,%5,%6,%7}, {%8,%9}, {%0,%1,%2,%3};"
        : "+f"(d[0]), "+f"(d[1]), "+f"(d[2]), "+f"(d[3])
        : "r"(a[0]), "r"(a[1]), "r"(a[2]), "r"(a[3]), "r"(b[0]), "r"(b[1]));
}
__device__ __forceinline__ void ldsm_x4(uint32_t& r0, uint32_t& r1,
                                        uint32_t& r2, uint32_t& r3, uint32_t addr) {
    asm volatile("ldmatrix.sync.aligned.m8n8.x4.shared.b16 {%0,%1,%2,%3}, [%4];"
                 : "=r"(r0), "=r"(r1), "=r"(r2), "=r"(r3) : "r"(addr));
}
__device__ __forceinline__ float ex2(float s) {
    float r;
    asm("ex2.approx.f32 %0, %1;" : "=f"(r) : "f"(s));
    return r;
}

// ---------------- one-shot conversion + weight transposes ----------------
__device__ void trans_tile(const float* __restrict__ src, __half* __restrict__ dst,
                           int K, int N, int ldk, int tk, int tn, bool w2remap)
{
    __shared__ float tl[32][33];
    int tx = threadIdx.x & 31, ty = threadIdx.x >> 5;
    int k0 = tk * 32, n0 = tn * 32;
#pragma unroll
    for (int i = 0; i < 4; i++) {
        int k = k0 + ty + i * 8, n = n0 + tx;
        tl[ty + i * 8][tx] = (k < K && n < N) ? src[(size_t)k * N + n] : 0.f;
    }
    __syncthreads();
#pragma unroll
    for (int i = 0; i < 4; i++) {
        int n = n0 + ty + i * 8, k = k0 + tx;
        if (n < N && k < K) {
            int kk = w2remap ? k + 3 * (k / 405) : k;
            dst[(size_t)n * ldk + kk] = __float2half_rn(tl[tx][ty + i * 8]);
        }
    }
}

__global__ void conv_all(const float* __restrict__ x,  const float* __restrict__ Wq,
                         const float* __restrict__ Wk, const float* __restrict__ Wv,
                         const float* __restrict__ Win, const float* __restrict__ W1,
                         const float* __restrict__ W2)
{
    int b = blockIdx.x;
    if (b < 256) {
#pragma unroll
        for (int u = 0; u < 8; u++) {
            int i = b * 2048 + u * 256 + threadIdx.x;
            float4 v = *(const float4*)(x + (size_t)i * 4);
            __half2 h0 = __floats2half2_rn(v.x, v.y);
            __half2 h1 = __floats2half2_rn(v.z, v.w);
            *(uint32_t*)(g_xc + (size_t)i * 4)     = *(uint32_t*)&h0;
            *(uint32_t*)(g_xc + (size_t)i * 4 + 2) = *(uint32_t*)&h1;
        }
    } else if (b < 512) {
        int i = b - 256;  trans_tile(Wq, g_wqt, 512, 512, 512, i / 16, i % 16, false);
    } else if (b < 768) {
        int i = b - 512;  trans_tile(Wk, g_wkt, 512, 512, 512, i / 16, i % 16, false);
    } else if (b < 1024) {
        int i = b - 768;  trans_tile(Wv, g_wvt, 512, 512, 512, i / 16, i % 16, false);
    } else if (b < 1056) {
        int i = b - 1024; trans_tile(Win, g_wint, 512, 64, 512, i / 2, i % 2, false);
    } else if (b < 1316) {
        int i = b - 1056; int r = i / 65, rem = i % 65;
        trans_tile(W1 + (size_t)r * DIN1 * INTER, g_w1t + (size_t)r * INTP * DIN1,
                   DIN1, INTER, DIN1, rem / 13, rem % 13, false);
    } else {
        int i = b - 1316;
        trans_tile(W2, g_w2t, 1620, 512, HSLDP, i / 16, i % 16, true);
    }
}

// ============================================================
// QKV + in_proj GEMM: CTA 64(M) x 128(N), 8 warps, warp 16x64,
// KC=64, 2-stage cp.async + ldmatrix. 3 CTAs/SM (24 warps).
// ============================================================
#define KC     64
#define LDH    72
#define ABUFH  (64 * LDH)
#define BBUFH  (128 * LDH)
#define BUFH   (ABUFH + BBUFH)
#define GEMM_SMEM (2 * BUFH * 2)   /* 55296 B */

__global__ void __launch_bounds__(256, 3) mma_gemm0(
    const float* __restrict__ bq, const float* __restrict__ bk,
    const float* __restrict__ bv, const float* __restrict__ b_in)
{
    extern __shared__ __half dynsh[];
    const uint32_t smbase = smem_u32(dynsh);

    const int tid = threadIdx.x;
    const int wid = tid >> 5, lane = tid & 31;
    const int wm = wid >> 1, wn = wid & 1;      // wm 0..3 (16 rows), wn 0..1 (64 cols)
    const int g = lane >> 2, tq = lane & 3;
    const int l8 = lane & 7, lm = lane >> 3;
    const int m_base = blockIdx.y * 64;
    const int n_base = blockIdx.x * 128;
    const int z = blockIdx.z;

    const __half* A = g_xc + (size_t)m_base * DIMN;
    const __half* Bt; const float* bias;
    int Nrows;
    if (z == 3) {
        if (blockIdx.x != 0) return;
        Bt = g_wint; Nrows = 64; bias = b_in;
    } else {
        Bt = (z == 0) ? g_wqt : (z == 1) ? g_wkt : g_wvt;
        Nrows = 512;
        bias = (z == 0) ? bq : (z == 1) ? bk : bv;
    }
    const int K = DIMN;
    const int KT = K / KC;   // 8

    float d[8][4];
#pragma unroll
    for (int j = 0; j < 8; j++)
#pragma unroll
        for (int c = 0; c < 4; c++) d[j][c] = 0.f;

    const uint32_t offA = (uint32_t)(((wm * 16 + (lm & 1) * 8 + l8) * LDH
                                      + (lm >> 1) * 8) * 2);
    uint32_t offB[4];
#pragma unroll
    for (int jj = 0; jj < 4; jj++)
        offB[jj] = (uint32_t)(((wn * 64 + jj * 16 + (lm >> 1) * 8 + l8) * LDH
                               + (lm & 1) * 8) * 2);

#define ISSUE(k0, buf)                                                         \
    do {                                                                       \
        uint32_t sA = smbase + (uint32_t)((buf) * BUFH) * 2u;                  \
        uint32_t sB = sA + (uint32_t)ABUFH * 2u;                               \
        _Pragma("unroll")                                                      \
        for (int i = 0; i < 2; i++) {         /* A: 64 rows x 8 grp */         \
            int idx = tid + (i << 8);                                          \
            int row = idx >> 3, grp = idx & 7;                                 \
            int kk = (k0) + grp * 8;                                           \
            cp16(sA + (uint32_t)(row * LDH + grp * 8) * 2u,                    \
                 A + (size_t)row * DIMN + kk, true);                           \
        }                                                                      \
        _Pragma("unroll")                                                      \
        for (int i = 0; i < 4; i++) {         /* B: 128 rows x 8 grp */        \
            int idx = tid + (i << 8);                                          \
            int row = idx >> 3, grp = idx & 7;                                 \
            int kk = (k0) + grp * 8;                                           \
            bool pb = (n_base + row) < Nrows;                                  \
            int brow = pb ? (n_base + row) : 0;                                \
            cp16(sB + (uint32_t)(row * LDH + grp * 8) * 2u,                    \
                 Bt + (size_t)brow * DIMN + kk, pb);                           \
        }                                                                      \
    } while (0)

    ISSUE(0, 0);
    CP_COMMIT();
    ISSUE(KC, 1);
    CP_COMMIT();
    CP_WAIT1();
    __syncthreads();

    for (int t = 0; t < KT; t++) {
        const uint32_t aB = smbase + (uint32_t)((t & 1) * BUFH) * 2u;
        const uint32_t bB = aB + (uint32_t)ABUFH * 2u;
#pragma unroll
        for (int ks = 0; ks < 4; ks++) {
            const uint32_t kof = (uint32_t)(ks * 32);
            uint32_t bf[8][2];
#pragma unroll
            for (int jj = 0; jj < 4; jj++)
                ldsm_x4(bf[2 * jj][0], bf[2 * jj][1],
                        bf[2 * jj + 1][0], bf[2 * jj + 1][1], bB + offB[jj] + kof);
            uint32_t af[4];
            ldsm_x4(af[0], af[1], af[2], af[3], aB + offA + kof);
#pragma unroll
            for (int j = 0; j < 8; j++)
                mma_f16(d[j], af, bf[j]);
        }
        __syncthreads();
        if (t + 2 < KT) { ISSUE((t + 2) * KC, t & 1); CP_COMMIT(); }
        if (t + 1 < KT) {
            if (t + 2 < KT) CP_WAIT1(); else CP_WAIT0();
            __syncthreads();
        }
    }

    // ---------------- epilogue ----------------
    int mr[2];
    mr[0] = m_base + wm * 16 + g;
    mr[1] = mr[0] + 8;
#pragma unroll
    for (int j = 0; j < 8; j++) {
        int n0 = n_base + wn * 64 + j * 8 + tq * 2;
#pragma unroll
        for (int rr = 0; rr < 2; rr++) {
            float v0 = d[j][rr * 2 + 0];
            float v1 = d[j][rr * 2 + 1];
            int m = mr[rr];
            if (z == 3) {
                if (n0 < 64) {
                    int r0i = n0 >> 4, d0i = n0 & 15;
                    int r1i = (n0 + 1) >> 4, d1i = (n0 + 1) & 15;
                    g_h1[(size_t)m * H1LD + r0i * DIN1 + 128 + d0i] =
                        __float2half_rn(v0 + bias[n0]);
                    g_h1[(size_t)m * H1LD + r1i * DIN1 + 128 + d1i] =
                        __float2half_rn(v1 + bias[n0 + 1]);
                }
            } else {
                __half* C = g_qkv + (size_t)z * TOK * DIMN;
                *(__half2*)(C + (size_t)m * DIMN + n0) =
                    __floats2half2_rn(v0 + bias[n0], v1 + bias[n0 + 1]);
            }
        }
    }
#undef ISSUE
}

// ============================================================
// MLP1 GEMM: CTA 64(M) x 128(N), K=144 resident, warp 16x64,
// 3 CTAs/SM. LDK1=152 keeps ldmatrix conflict-free.
// ============================================================
#define LDK1   152
#define M1ABUF (64 * LDK1)
#define M1BBUF (128 * LDK1)
#define MLP1_SMEM ((M1ABUF + M1BBUF) * 2)   /* 58368 B */

__global__ void __launch_bounds__(256, 3) mlp1_gemm(
    const float* __restrict__ b1, const float* __restrict__ rs)
{
    extern __shared__ __half dynsh[];
    const uint32_t smA = smem_u32(dynsh);
    const uint32_t smB = smA + (uint32_t)M1ABUF * 2u;

    const int tid = threadIdx.x;
    const int wid = tid >> 5, lane = tid & 31;
    const int wm = wid >> 1, wn = wid & 1;
    const int g = lane >> 2, tq = lane & 3;
    const int l8 = lane & 7, lm = lane >> 3;
    const int m_base = blockIdx.y * 64;
    const int n_base = blockIdx.x * 128;
    const int z = blockIdx.z;

    const __half* A = g_h1 + (size_t)m_base * H1LD + z * DIN1;
    const __half* Bt = g_w1t + (size_t)z * INTP * DIN1;
    const float* bias = b1 + z * INTER;

    // load A (64x18 grp = 1152) then B (128x18 = 2304): 3456 cp16, 14 rounds
#pragma unroll
    for (int i = 0; i < 14; i++) {
        int idx = tid + (i << 8);
        if (idx < 1152) {
            int row = idx / 18, grp = idx % 18;
            cp16(smA + (uint32_t)(row * LDK1 + grp * 8) * 2u,
                 A + (size_t)row * H1LD + grp * 8, true);
        } else if (idx < 3456) {
            int idx2 = idx - 1152;
            int row = idx2 / 18, grp = idx2 % 18;
            bool pb = (n_base + row) < INTP;
            int brow = pb ? (n_base + row) : 0;
            cp16(smB + (uint32_t)(row * LDK1 + grp * 8) * 2u,
                 Bt + (size_t)brow * DIN1 + grp * 8, pb);
        }
    }
    CP_COMMIT();
    CP_WAIT0();
    __syncthreads();

    const uint32_t offA = (uint32_t)(((wm * 16 + (lm & 1) * 8 + l8) * LDK1
                                      + (lm >> 1) * 8) * 2);
    uint32_t offB[4];
#pragma unroll
    for (int jj = 0; jj < 4; jj++)
        offB[jj] = (uint32_t)(((wn * 64 + jj * 16 + (lm >> 1) * 8 + l8) * LDK1
                               + (lm & 1) * 8) * 2);

    float d[8][4];
#pragma unroll
    for (int j = 0; j < 8; j++)
#pragma unroll
        for (int c = 0; c < 4; c++) d[j][c] = 0.f;

#pragma unroll
    for (int ks = 0; ks < 9; ks++) {       // 9 * 16 = 144
        const uint32_t kof = (uint32_t)(ks * 32);
        uint32_t bf[8][2];
#pragma unroll
        for (int jj = 0; jj < 4; jj++)
            ldsm_x4(bf[2 * jj][0], bf[2 * jj][1],
                    bf[2 * jj + 1][0], bf[2 * jj + 1][1], smB + offB[jj] + kof);
        uint32_t af[4];
        ldsm_x4(af[0], af[1], af[2], af[3], smA + offA + kof);
#pragma unroll
        for (int j = 0; j < 8; j++)
            mma_f16(d[j], af, bf[j]);
    }

    // epilogue: relu * rs + b1 -> g_hs (fp16)
    int mr[2];
    mr[0] = m_base + wm * 16 + g;
    mr[1] = mr[0] + 8;
#pragma unroll
    for (int j = 0; j < 8; j++) {
        int n0 = n_base + wn * 64 + j * 8 + tq * 2;
#pragma unroll
        for (int rr = 0; rr < 2; rr++) {
            float v0 = d[j][rr * 2 + 0];
            float v1 = d[j][rr * 2 + 1];
            int m = mr[rr];
            float rsv = rs[m * RNUM + z];
            size_t base = (size_t)m * HSLDP + z * INTP + n0;
            if (n0 + 1 < INTER) {
                *(__half2*)(g_hs + base) = __floats2half2_rn(
                    fmaxf(v0 + bias[n0], 0.f) * rsv,
                    fmaxf(v1 + bias[n0 + 1], 0.f) * rsv);
            } else if (n0 < INTER) {
                g_hs[base] = __float2half_rn(fmaxf(v0 + bias[n0], 0.f) * rsv);
            }
        }
    }
}

// ============================================================
// MLP2 GEMM (unchanged R14): 128x64 tile, warp 32x32, occ 3,
// ks-skip on the 32-valid last chunk. +sum_r rs*b2 -> out + rs tail.
// ============================================================
#define BUFH64 ((128 + 64) * LDH)
#define GEMM64_SMEM (2 * BUFH64 * 2)

__global__ void __launch_bounds__(256, 3) mma_gemm64(
    const float* __restrict__ b2, const float* __restrict__ rs,
    float* __restrict__ out)
{
    extern __shared__ __half dynsh[];
    const uint32_t smbase = smem_u32(dynsh);

    const int tid = threadIdx.x;
    const int wid = tid >> 5, lane = tid & 31;
    const int wm = wid >> 1, wn = wid & 1;
    const int g = lane >> 2, tq = lane & 3;
    const int m_base = blockIdx.y * 128;
    const int n_base = blockIdx.x * 64;

    const __half* A = g_hs + (size_t)m_base * HSLDP;
    const __half* Bt = g_w2t + (size_t)n_base * HSLDP;
    const int K = HSLDP;
    const int NKT = (K + KC - 1) / KC;   // 26

    float d[2][4][4];
#pragma unroll
    for (int i = 0; i < 2; i++)
#pragma unroll
        for (int j = 0; j < 4; j++)
#pragma unroll
            for (int c = 0; c < 4; c++) d[i][j][c] = 0.f;

    const int l8 = lane & 7, lm = lane >> 3;
    const uint32_t offA0 = (uint32_t)(((wm * 32 + (lm & 1) * 8 + l8) * LDH
                                       + (lm >> 1) * 8) * 2);
    const uint32_t offA1 = offA0 + (uint32_t)(16 * LDH * 2);
    uint32_t offB[2];
#pragma unroll
    for (int jj = 0; jj < 2; jj++)
        offB[jj] = (uint32_t)(((128 + wn * 32 + jj * 16 + (lm >> 1) * 8 + l8) * LDH
                               + (lm & 1) * 8) * 2);

#define ISSUE64(k0, buf)                                                       \
    do {                                                                       \
        uint32_t sS = smbase + (uint32_t)((buf) * BUFH64) * 2u;                \
        _Pragma("unroll")                                                      \
        for (int i = 0; i < 4; i++) {                                          \
            int idx = tid + (i << 8);                                          \
            int row = idx >> 3, grp = idx & 7;                                 \
            int kk = (k0) + grp * 8;                                           \
            bool pk = kk < K;                                                  \
            int kcl = pk ? kk : 0;                                             \
            cp16(sS + (uint32_t)(row * LDH + grp * 8) * 2u,                    \
                 A + (size_t)row * HSLDP + kcl, pk);                           \
        }                                                                      \
        _Pragma("unroll")                                                      \
        for (int i = 0; i < 2; i++) {                                          \
            int idx = tid + (i << 8);                                          \
            int row = idx >> 3, grp = idx & 7;                                 \
            int kk = (k0) + grp * 8;                                           \
            bool pk = kk < K;                                                  \
            int kcl = pk ? kk : 0;                                             \
            cp16(sS + (uint32_t)((128 + row) * LDH + grp * 8) * 2u,            \
                 Bt + (size_t)row * HSLDP + kcl, pk);                          \
        }                                                                      \
    } while (0)

    ISSUE64(0, 0);
    CP_COMMIT();
    ISSUE64(KC, 1);
    CP_COMMIT();
    CP_WAIT1();
    __syncthreads();

    for (int t = 0; t < NKT; t++) {
        const uint32_t sS = smbase + (uint32_t)((t & 1) * BUFH64) * 2u;
        const int krem = K - t * KC;
#pragma unroll
        for (int ks = 0; ks < 4; ks++) {
            if (ks * 16 >= krem) break;
            const uint32_t kof = (uint32_t)(ks * 32);
            uint32_t bf[4][2];
#pragma unroll
            for (int jj = 0; jj < 2; jj++)
                ldsm_x4(bf[2 * jj][0], bf[2 * jj][1],
                        bf[2 * jj + 1][0], bf[2 * jj + 1][1], sS + offB[jj] + kof);
            uint32_t af0[4], af1[4];
            ldsm_x4(af0[0], af0[1], af0[2], af0[3], sS + offA0 + kof);
            ldsm_x4(af1[0], af1[1], af1[2], af1[3], sS + offA1 + kof);
#pragma unroll
            for (int j = 0; j < 4; j++) {
                mma_f16(d[0][j], af0, bf[j]);
                mma_f16(d[1][j], af1, bf[j]);
            }
        }
        __syncthreads();
        if (t + 2 < NKT) { ISSUE64((t + 2) * KC, t & 1); CP_COMMIT(); }
        if (t + 1 < NKT) {
            if (t + 2 < NKT) CP_WAIT1(); else CP_WAIT0();
            __syncthreads();
        }
    }

#pragma unroll
    for (int i = 0; i < 2; i++) {
        int mr[2];
        mr[0] = m_base + wm * 32 + i * 16 + g;
        mr[1] = mr[0] + 8;
#pragma unroll
        for (int j = 0; j < 4; j++) {
            int n0 = n_base + wn * 32 + j * 8 + tq * 2;
#pragma unroll
            for (int rr = 0; rr < 2; rr++) {
                float v0 = d[i][j][rr * 2 + 0];
                float v1 = d[i][j][rr * 2 + 1];
                int m = mr[rr];
                float4 q = *(const float4*)(rs + m * RNUM);
                float c0 = q.x * b2[n0]            + q.y * b2[DIMN + n0]
                         + q.z * b2[2 * DIMN + n0] + q.w * b2[3 * DIMN + n0];
                float c1 = q.x * b2[n0 + 1]            + q.y * b2[DIMN + n0 + 1]
                         + q.z * b2[2 * DIMN + n0 + 1] + q.w * b2[3 * DIMN + n0 + 1];
                *(float2*)(out + (size_t)m * DIMN + n0) =
                    make_float2(v0 + c0, v1 + c1);
            }
        }
    }

    if (blockIdx.x == 0) {
        int idx = blockIdx.y * 512 + tid * 2;
        *(float2*)(out + (size_t)TOK * DIMN + idx) = *(const float2*)(rs + idx);
    }
#undef ISSUE64
}

// ============================================================
// Flash attention (unchanged R13: ldmatrix + ex2, occupancy 3).
// ============================================================
#define LDQH 24
#define LDPH 136
#define FA_SMEM ((128 * LDQH * 2 + 16 * LDPH + 128 * LDPH) * 2)
#define QK_SCALE 0.360673760222241f

__global__ void __launch_bounds__(256, 3) fa_kernel()
{
    extern __shared__ __half fsh[];
    __half* Qs = fsh;
    __half* Ks = fsh + 128 * LDQH;
    __half* Vs = fsh + 2 * 128 * LDQH;
    __half* Ps = Vs + 16 * LDPH;
    const uint32_t uQs = smem_u32(Qs);
    const uint32_t uKs = smem_u32(Ks);
    const uint32_t uVs = smem_u32(Vs);
    const uint32_t uPs = smem_u32(Ps);

    const int qt = blockIdx.x;
    const int gg = blockIdx.y;
    const int bb = blockIdx.z;
    const int r = gg >> 3, hh = gg & 7;
    const int tid = threadIdx.x;
    const int wid = tid >> 5, lane = tid & 31;
    const int g = lane >> 2, tq = lane & 3;
    const int l8 = lane & 7, lm = lane >> 3;

    const __half* gq = g_qkv;
    const __half* gk = g_qkv + (size_t)TOK * DIMN;
    const __half* gv = g_qkv + 2 * (size_t)TOK * DIMN;
    const int seq0 = bb * NSEQ;

    const __half2 qscale = __floats2half2_rn(QK_SCALE, QK_SCALE);

    {
        int row = tid >> 1, part = tid & 1;
        int tok = seq0 + qt * 128 + row;
        uint4 v = *(const uint4*)(gq + (size_t)tok * DIMN + gg * HD + part * 8);
        __half2* pv = (__half2*)&v;
#pragma unroll
        for (int l = 0; l < 4; l++) pv[l] = __hmul2(pv[l], qscale);
        *(uint4*)(Qs + row * LDQH + part * 8) = v;
    }

    float o[2][4];
#pragma unroll
    for (int j = 0; j < 2; j++)
#pragma unroll
        for (int c = 0; c < 4; c++) o[j][c] = 0.f;
    float lsum[2] = {0.f, 0.f};

    const int row0 = wid * 16 + g;

    const uint32_t offQA = (uint32_t)(((wid * 16 + (lm & 1) * 8 + l8) * LDQH
                                       + (lm >> 1) * 8) * 2);
    uint32_t offKB[4];
#pragma unroll
    for (int jj = 0; jj < 4; jj++)
        offKB[jj] = (uint32_t)(((jj * 16 + (lm >> 1) * 8 + l8) * LDQH
                                + (lm & 1) * 8) * 2);
    const uint32_t offPA = (uint32_t)(((wid * 16 + (lm & 1) * 8 + l8) * LDPH
                                       + (lm >> 1) * 8) * 2);
    const uint32_t offVB = (uint32_t)((((lm >> 1) * 8 + l8) * LDPH
                                       + (lm & 1) * 8) * 2);

    for (int jt = 0; jt < 4; jt++) {
        {
            int row = tid >> 1, part = tid & 1;
            int tok = seq0 + jt * 128 + row;
            uint4 kv = *(const uint4*)(gk + (size_t)tok * DIMN + gg * HD + part * 8);
            *(uint4*)(Ks + row * LDQH + part * 8) = kv;
            uint4 vv = *(const uint4*)(gv + (size_t)tok * DIMN + gg * HD + part * 8);
            __half tmp[8];
            *(uint4*)tmp = vv;
            int d0 = part * 8;
#pragma unroll
            for (int l = 0; l < 8; l++) Vs[(d0 + l) * LDPH + row] = tmp[l];
        }
        __syncthreads();

        uint32_t af[4];
        ldsm_x4(af[0], af[1], af[2], af[3], uQs + offQA);

#pragma unroll
        for (int hn = 0; hn < 2; hn++) {
            const uint32_t hof = (uint32_t)(hn * 64 * LDQH * 2);
            uint32_t bf[8][2];
#pragma unroll
            for (int jj = 0; jj < 4; jj++)
                ldsm_x4(bf[2 * jj][0], bf[2 * jj][1],
                        bf[2 * jj + 1][0], bf[2 * jj + 1][1],
                        uKs + offKB[jj] + hof);
            float s[8][4];
#pragma unroll
            for (int jn = 0; jn < 8; jn++) {
#pragma unroll
                for (int c = 0; c < 4; c++) s[jn][c] = 0.f;
                mma_f16(s[jn], af, bf[jn]);
            }
#pragma unroll
            for (int jn = 0; jn < 8; jn++) {
                int c0 = hn * 64 + jn * 8 + 2 * tq;
                int gc0 = jt * 128 + c0;
#pragma unroll
                for (int rr = 0; rr < 2; rr++) {
                    int rl = row0 + rr * 8;
                    int grow = qt * 128 + rl;
                    float p0 = ex2(s[jn][rr * 2 + 0]);
                    float p1 = ex2(s[jn][rr * 2 + 1]);
                    if (gc0 == grow)     p0 = 0.f;
                    if (gc0 + 1 == grow) p1 = 0.f;
                    lsum[rr] += p0 + p1;
                    *(__half2*)(Ps + rl * LDPH + c0) = __floats2half2_rn(p0, p1);
                }
            }
        }
        __syncthreads();

#pragma unroll
        for (int ksi = 0; ksi < 8; ksi++) {
            const uint32_t kof = (uint32_t)(ksi * 32);
            uint32_t pa[4];
            ldsm_x4(pa[0], pa[1], pa[2], pa[3], uPs + offPA + kof);
            uint32_t bf[2][2];
            ldsm_x4(bf[0][0], bf[0][1], bf[1][0], bf[1][1], uVs + offVB + kof);
            mma_f16(o[0], pa, bf[0]);
            mma_f16(o[1], pa, bf[1]);
        }
        __syncthreads();
    }

#pragma unroll
    for (int rr = 0; rr < 2; rr++) {
        lsum[rr] += __shfl_xor_sync(0xFFFFFFFF, lsum[rr], 1);
        lsum[rr] += __shfl_xor_sync(0xFFFFFFFF, lsum[rr], 2);
    }
    float inv[2] = {1.f / lsum[0], 1.f / lsum[1]};

#pragma unroll
    for (int rr = 0; rr < 2; rr++) {
        int tok = seq0 + qt * 128 + row0 + rr * 8;
        __half* dst = g_h1 + (size_t)tok * H1LD + r * DIN1 + hh * HD;
#pragma unroll
        for (int jn = 0; jn < 2; jn++) {
            int col = jn * 8 + 2 * tq;
            *(__half2*)(dst + col) = __floats2half2_rn(o[jn][rr * 2 + 0] * inv[rr],
                                                       o[jn][rr * 2 + 1] * inv[rr]);
        }
    }
}

// ============================================================
extern "C" void kernel_launch(void* const* d_in, const int* in_sizes, int n_in,
                              void* d_out, int out_size)
{
    const float* x    = (const float*)d_in[0];
    const float* rs   = (const float*)d_in[1];
    const float* Wq   = (const float*)d_in[2];
    const float* bq   = (const float*)d_in[3];
    const float* Wk   = (const float*)d_in[4];
    const float* bk   = (const float*)d_in[5];
    const float* Wv   = (const float*)d_in[6];
    const float* bv   = (const float*)d_in[7];
    const float* Win  = (const float*)d_in[8];
    const float* b_in = (const float*)d_in[9];
    const float* W1   = (const float*)d_in[10];
    const float* b1   = (const float*)d_in[11];
    const float* W2   = (const float*)d_in[12];
    const float* b2   = (const float*)d_in[13];
    float* out = (float*)d_out;

    cudaFuncSetAttribute(mma_gemm0, cudaFuncAttributeMaxDynamicSharedMemorySize, GEMM_SMEM);
    cudaFuncSetAttribute(mlp1_gemm, cudaFuncAttributeMaxDynamicSharedMemorySize, MLP1_SMEM);
    cudaFuncSetAttribute(mma_gemm64, cudaFuncAttributeMaxDynamicSharedMemorySize, GEMM64_SMEM);
    cudaFuncSetAttribute(fa_kernel, cudaFuncAttributeMaxDynamicSharedMemorySize, FA_SMEM);

    conv_all<<<2132, 256>>>(x, Wq, Wk, Wv, Win, W1, W2);

    mma_gemm0<<<dim3(4, 64, 4), 256, GEMM_SMEM>>>(bq, bk, bv, b_in);
    fa_kernel<<<dim3(4, GQ, 8), 256, FA_SMEM>>>();
    mlp1_gemm<<<dim3(4, 64, 4), 256, MLP1_SMEM>>>(b1, rs);
    mma_gemm64<<<dim3(8, 32), 256, GEMM64_SMEM>>>(b2, rs, out);
}

// round 17
// speedup vs baseline: 1.0704x; 1.0704x over previous
#include <cuda_runtime.h>
#include <cuda_fp16.h>
#include <cstdint>

#define TOK   4096
#define DIMN  512
#define GQ    32
#define HD    16
#define RNUM  4
#define INTER 405
#define INTP  408
#define DIN1  144
#define H1LD  576
#define HSLDP 1632
#define NSEQ  512

// ---------------- device scratch (fp16 payloads) ----------------
__device__ __half g_xc[TOK * DIMN];
__device__ __half g_wqt[DIMN * DIMN];
__device__ __half g_wkt[DIMN * DIMN];
__device__ __half g_wvt[DIMN * DIMN];
__device__ __half g_wint[64 * DIMN];
__device__ __half g_w1t[RNUM * INTP * DIN1];
__device__ __half g_w2t[DIMN * HSLDP];
__device__ __half g_qkv[3 * TOK * DIMN];
__device__ __half g_h1[TOK * H1LD];
__device__ __half g_hs[TOK * HSLDP];

// ---------------- helpers ----------------
__device__ __forceinline__ uint32_t smem_u32(const void* p) {
    uint32_t a;
    asm("{ .reg .u64 t; cvta.to.shared.u64 t, %1; cvt.u32.u64 %0, t; }"
        : "=r"(a) : "l"(p));
    return a;
}
__device__ __forceinline__ void cp16(uint32_t dst, const void* src, bool pred) {
    int sz = pred ? 16 : 0;
    asm volatile("cp.async.ca.shared.global [%0], [%1], 16, %2;"
                 :: "r"(dst), "l"(src), "r"(sz) : "memory");
}
#define CP_COMMIT() asm volatile("cp.async.commit_group;" ::: "memory")
#define CP_WAIT1()  asm volatile("cp.async.wait_group 1;" ::: "memory")
#define CP_WAIT0()  asm volatile("cp.async.wait_group 0;" ::: "memory")

__device__ __forceinline__ void mma_f16(float d[4], const uint32_t a[4],
                                        const uint32_t b[2]) {
    asm volatile(
        "mma.sync.aligned.m16n8k16.row.col.f32.f16.f16.f32 "
        "{%0,%1,%2,%3}, {%4,%5,%6,%7}, {%8,%9}, {%0,%1,%2,%3};"
        : "+f"(d[0]), "+f"(d[1]), "+f"(d[2]), "+f"(d[3])
        : "r"(a[0]), "r"(a[1]), "r"(a[2]), "r"(a[3]), "r"(b[0]), "r"(b[1]));
}
__device__ __forceinline__ void ldsm_x4(uint32_t& r0, uint32_t& r1,
                                        uint32_t& r2, uint32_t& r3, uint32_t addr) {
    asm volatile("ldmatrix.sync.aligned.m8n8.x4.shared.b16 {%0,%1,%2,%3}, [%4];"
                 : "=r"(r0), "=r"(r1), "=r"(r2), "=r"(r3) : "r"(addr));
}
__device__ __forceinline__ float ex2(float s) {
    float r;
    asm("ex2.approx.f32 %0, %1;" : "=f"(r) : "f"(s));
    return r;
}

// ---------------- one-shot conversion + weight transposes ----------------
__device__ void trans_tile(const float* __restrict__ src, __half* __restrict__ dst,
                           int K, int N, int ldk, int tk, int tn, bool w2remap)
{
    __shared__ float tl[32][33];
    int tx = threadIdx.x & 31, ty = threadIdx.x >> 5;
    int k0 = tk * 32, n0 = tn * 32;
#pragma unroll
    for (int i = 0; i < 4; i++) {
        int k = k0 + ty + i * 8, n = n0 + tx;
        tl[ty + i * 8][tx] = (k < K && n < N) ? src[(size_t)k * N + n] : 0.f;
    }
    __syncthreads();
#pragma unroll
    for (int i = 0; i < 4; i++) {
        int n = n0 + ty + i * 8, k = k0 + tx;
        if (n < N && k < K) {
            int kk = w2remap ? k + 3 * (k / 405) : k;
            dst[(size_t)n * ldk + kk] = __float2half_rn(tl[tx][ty + i * 8]);
        }
    }
}

__global__ void conv_all(const float* __restrict__ x,  const float* __restrict__ Wq,
                         const float* __restrict__ Wk, const float* __restrict__ Wv,
                         const float* __restrict__ Win, const float* __restrict__ W1,
                         const float* __restrict__ W2)
{
    int b = blockIdx.x;
    if (b < 256) {
#pragma unroll
        for (int u = 0; u < 8; u++) {
            int i = b * 2048 + u * 256 + threadIdx.x;
            float4 v = *(const float4*)(x + (size_t)i * 4);
            __half2 h0 = __floats2half2_rn(v.x, v.y);
            __half2 h1 = __floats2half2_rn(v.z, v.w);
            *(uint32_t*)(g_xc + (size_t)i * 4)     = *(uint32_t*)&h0;
            *(uint32_t*)(g_xc + (size_t)i * 4 + 2) = *(uint32_t*)&h1;
        }
    } else if (b < 512) {
        int i = b - 256;  trans_tile(Wq, g_wqt, 512, 512, 512, i / 16, i % 16, false);
    } else if (b < 768) {
        int i = b - 512;  trans_tile(Wk, g_wkt, 512, 512, 512, i / 16, i % 16, false);
    } else if (b < 1024) {
        int i = b - 768;  trans_tile(Wv, g_wvt, 512, 512, 512, i / 16, i % 16, false);
    } else if (b < 1056) {
        int i = b - 1024; trans_tile(Win, g_wint, 512, 64, 512, i / 2, i % 2, false);
    } else if (b < 1316) {
        int i = b - 1056; int r = i / 65, rem = i % 65;
        trans_tile(W1 + (size_t)r * DIN1 * INTER, g_w1t + (size_t)r * INTP * DIN1,
                   DIN1, INTER, DIN1, rem / 13, rem % 13, false);
    } else {
        int i = b - 1316;
        trans_tile(W2, g_w2t, 1620, 512, HSLDP, i / 16, i % 16, true);
    }
}

// ============================================================
// fp16 mma GEMM 128x128 (modes 0, 2): KC=64, 8 warps, warp 32x64,
// 2-stage cp.async + ldmatrix, ks-skip. MODE 0 z<3 uses smem-staged
// coalesced epilogue (16B STG) instead of scattered 4B stores.
// ============================================================
#define KC     64
#define LDH    72
#define ABUFH  (128 * LDH)
#define BBUFH  (128 * LDH)
#define BUFH   (ABUFH + BBUFH)
#define GEMM_SMEM (2 * BUFH * 2)
#define LDE    136   /* staging row stride in halves */

template<int MODE>
__global__ void __launch_bounds__(256, 2) mma_gemm(
    const float* __restrict__ bq, const float* __restrict__ bk,
    const float* __restrict__ bv, const float* __restrict__ b_in,
    const float* __restrict__ b1, const float* __restrict__ rs)
{
    extern __shared__ __half dynsh[];
    const uint32_t smbase = smem_u32(dynsh);

    const int tid = threadIdx.x;
    const int wid = tid >> 5, lane = tid & 31;
    const int wm = wid >> 1, wn = wid & 1;
    const int g = lane >> 2, tq = lane & 3;
    const int m_base = blockIdx.y * 128;
    const int n_base = blockIdx.x * 128;
    const int z = blockIdx.z;

    const __half* A; const __half* Bt; const float* bias;
    int lda, K, Nrows, ldbk;
    if (MODE == 0) {
        A = g_xc + (size_t)m_base * DIMN; lda = DIMN; K = DIMN;
        if (z == 3) {
            if (blockIdx.x != 0) return;
            Bt = g_wint; Nrows = 64; ldbk = DIMN; bias = b_in;
        } else {
            Bt = (z == 0) ? g_wqt : (z == 1) ? g_wkt : g_wvt;
            Nrows = 512; ldbk = DIMN;
            bias = (z == 0) ? bq : (z == 1) ? bk : bv;
        }
    } else {
        A = g_h1 + (size_t)m_base * H1LD + z * DIN1; lda = H1LD; K = DIN1;
        Bt = g_w1t + (size_t)z * INTP * DIN1; Nrows = INTP; ldbk = DIN1;
        bias = b1 + z * INTER;
    }

    float d[2][8][4];
#pragma unroll
    for (int i = 0; i < 2; i++)
#pragma unroll
        for (int j = 0; j < 8; j++)
#pragma unroll
            for (int c = 0; c < 4; c++) d[i][j][c] = 0.f;

    const int KT = (K + KC - 1) / KC;

    const int l8 = lane & 7, lm = lane >> 3;
    const uint32_t offA0 = (uint32_t)(((wm * 32 + (lm & 1) * 8 + l8) * LDH
                                       + (lm >> 1) * 8) * 2);
    const uint32_t offA1 = offA0 + (uint32_t)(16 * LDH * 2);
    uint32_t offB[4];
#pragma unroll
    for (int jj = 0; jj < 4; jj++)
        offB[jj] = (uint32_t)(((wn * 64 + jj * 16 + (lm >> 1) * 8 + l8) * LDH
                               + (lm & 1) * 8) * 2);

#define ISSUE(k0, buf)                                                         \
    do {                                                                       \
        uint32_t sA = smbase + (uint32_t)((buf) * BUFH) * 2u;                  \
        uint32_t sB = sA + (uint32_t)ABUFH * 2u;                               \
        _Pragma("unroll")                                                      \
        for (int i = 0; i < 4; i++) {                                          \
            int idx = tid + (i << 8);                                          \
            int row = idx >> 3, grp = idx & 7;                                 \
            int kk = (k0) + grp * 8;                                           \
            bool pk = kk < K;                                                  \
            int kcl = pk ? kk : 0;                                             \
            cp16(sA + (uint32_t)(row * LDH + grp * 8) * 2u,                    \
                 A + (size_t)row * lda + kcl, pk);                             \
            bool pb = pk && (n_base + row) < Nrows;                            \
            int brow = ((n_base + row) < Nrows) ? (n_base + row) : 0;          \
            cp16(sB + (uint32_t)(row * LDH + grp * 8) * 2u,                    \
                 Bt + (size_t)brow * ldbk + kcl, pb);                          \
        }                                                                      \
    } while (0)

    ISSUE(0, 0);
    CP_COMMIT();
    ISSUE(KC, 1);
    CP_COMMIT();
    CP_WAIT1();
    __syncthreads();

    for (int t = 0; t < KT; t++) {
        const uint32_t aB = smbase + (uint32_t)((t & 1) * BUFH) * 2u;
        const uint32_t bB = aB + (uint32_t)ABUFH * 2u;
        const int krem = K - t * KC;
#pragma unroll
        for (int ks = 0; ks < 4; ks++) {
            if (ks * 16 >= krem) break;
            const uint32_t kof = (uint32_t)(ks * 32);
            uint32_t bf[8][2];
#pragma unroll
            for (int jj = 0; jj < 4; jj++)
                ldsm_x4(bf[2 * jj][0], bf[2 * jj][1],
                        bf[2 * jj + 1][0], bf[2 * jj + 1][1], bB + offB[jj] + kof);
            uint32_t af0[4], af1[4];
            ldsm_x4(af0[0], af0[1], af0[2], af0[3], aB + offA0 + kof);
            ldsm_x4(af1[0], af1[1], af1[2], af1[3], aB + offA1 + kof);
#pragma unroll
            for (int j = 0; j < 8; j++) {
                mma_f16(d[0][j], af0, bf[j]);
                mma_f16(d[1][j], af1, bf[j]);
            }
        }
        __syncthreads();
        if (t + 2 < KT) { ISSUE((t + 2) * KC, t & 1); CP_COMMIT(); }
        if (t + 1 < KT) {
            if (t + 2 < KT) CP_WAIT1(); else CP_WAIT0();
            __syncthreads();
        }
    }

    // ---------------- epilogue ----------------
    if (MODE == 0 && z < 3) {
        // stage (value + bias) to smem, then coalesced 16B stores
        __half* stg = dynsh;   // pipeline buffers are free after last barrier
#pragma unroll
        for (int i = 0; i < 2; i++) {
#pragma unroll
            for (int j = 0; j < 8; j++) {
                int c0 = wn * 64 + j * 8 + tq * 2;
#pragma unroll
                for (int rr = 0; rr < 2; rr++) {
                    int rl = wm * 32 + i * 16 + g + rr * 8;
                    int n0 = n_base + c0;
                    *(__half2*)(stg + rl * LDE + c0) = __floats2half2_rn(
                        d[i][j][rr * 2 + 0] + bias[n0],
                        d[i][j][rr * 2 + 1] + bias[n0 + 1]);
                }
            }
        }
        __syncthreads();
        __half* C = g_qkv + (size_t)z * TOK * DIMN;
#pragma unroll
        for (int p = 0; p < 8; p++) {
            int idx = tid + (p << 8);
            int row = idx >> 4, seg = idx & 15;
            uint4 v = *(const uint4*)(stg + row * LDE + seg * 8);
            *(uint4*)(C + (size_t)(m_base + row) * DIMN + n_base + seg * 8) = v;
        }
        return;
    }

#pragma unroll
    for (int i = 0; i < 2; i++) {
        int mr[2];
        mr[0] = m_base + wm * 32 + i * 16 + g;
        mr[1] = mr[0] + 8;
#pragma unroll
        for (int j = 0; j < 8; j++) {
            int n0 = n_base + wn * 64 + j * 8 + tq * 2;
#pragma unroll
            for (int rr = 0; rr < 2; rr++) {
                float v0 = d[i][j][rr * 2 + 0];
                float v1 = d[i][j][rr * 2 + 1];
                int m = mr[rr];
                if (MODE == 0) {
                    // z == 3 (in_proj scatter)
                    if (n0 < 64) {
                        int r0i = n0 >> 4, d0i = n0 & 15;
                        int r1i = (n0 + 1) >> 4, d1i = (n0 + 1) & 15;
                        g_h1[(size_t)m * H1LD + r0i * DIN1 + 128 + d0i] =
                            __float2half_rn(v0 + bias[n0]);
                        g_h1[(size_t)m * H1LD + r1i * DIN1 + 128 + d1i] =
                            __float2half_rn(v1 + bias[n0 + 1]);
                    }
                } else {
                    float rsv = rs[m * RNUM + z];
                    size_t base = (size_t)m * HSLDP + z * INTP + n0;
                    if (n0 + 1 < INTER) {
                        *(__half2*)(g_hs + base) = __floats2half2_rn(
                            fmaxf(v0 + bias[n0], 0.f) * rsv,
                            fmaxf(v1 + bias[n0 + 1], 0.f) * rsv);
                    } else if (n0 < INTER) {
                        g_hs[base] = __float2half_rn(fmaxf(v0 + bias[n0], 0.f) * rsv);
                    }
                }
            }
        }
    }
#undef ISSUE
}

// ============================================================
// MLP2 GEMM (R14): 128x64 tile, warp 32x32, occ 3, ks-skip,
// +sum_r rs*b2 -> out + rs tail.
// ============================================================
#define BUFH64 ((128 + 64) * LDH)
#define GEMM64_SMEM (2 * BUFH64 * 2)

__global__ void __launch_bounds__(256, 3) mma_gemm64(
    const float* __restrict__ b2, const float* __restrict__ rs,
    float* __restrict__ out)
{
    extern __shared__ __half dynsh[];
    const uint32_t smbase = smem_u32(dynsh);

    const int tid = threadIdx.x;
    const int wid = tid >> 5, lane = tid & 31;
    const int wm = wid >> 1, wn = wid & 1;
    const int g = lane >> 2, tq = lane & 3;
    const int m_base = blockIdx.y * 128;
    const int n_base = blockIdx.x * 64;

    const __half* A = g_hs + (size_t)m_base * HSLDP;
    const __half* Bt = g_w2t + (size_t)n_base * HSLDP;
    const int K = HSLDP;
    const int NKT = (K + KC - 1) / KC;

    float d[2][4][4];
#pragma unroll
    for (int i = 0; i < 2; i++)
#pragma unroll
        for (int j = 0; j < 4; j++)
#pragma unroll
            for (int c = 0; c < 4; c++) d[i][j][c] = 0.f;

    const int l8 = lane & 7, lm = lane >> 3;
    const uint32_t offA0 = (uint32_t)(((wm * 32 + (lm & 1) * 8 + l8) * LDH
                                       + (lm >> 1) * 8) * 2);
    const uint32_t offA1 = offA0 + (uint32_t)(16 * LDH * 2);
    uint32_t offB[2];
#pragma unroll
    for (int jj = 0; jj < 2; jj++)
        offB[jj] = (uint32_t)(((128 + wn * 32 + jj * 16 + (lm >> 1) * 8 + l8) * LDH
                               + (lm & 1) * 8) * 2);

#define ISSUE64(k0, buf)                                                       \
    do {                                                                       \
        uint32_t sS = smbase + (uint32_t)((buf) * BUFH64) * 2u;                \
        _Pragma("unroll")                                                      \
        for (int i = 0; i < 4; i++) {                                          \
            int idx = tid + (i << 8);                                          \
            int row = idx >> 3, grp = idx & 7;                                 \
            int kk = (k0) + grp * 8;                                           \
            bool pk = kk < K;                                                  \
            int kcl = pk ? kk : 0;                                             \
            cp16(sS + (uint32_t)(row * LDH + grp * 8) * 2u,                    \
                 A + (size_t)row * HSLDP + kcl, pk);                           \
        }                                                                      \
        _Pragma("unroll")                                                      \
        for (int i = 0; i < 2; i++) {                                          \
            int idx = tid + (i << 8);                                          \
            int row = idx >> 3, grp = idx & 7;                                 \
            int kk = (k0) + grp * 8;                                           \
            bool pk = kk < K;                                                  \
            int kcl = pk ? kk : 0;                                             \
            cp16(sS + (uint32_t)((128 + row) * LDH + grp * 8) * 2u,            \
                 Bt + (size_t)row * HSLDP + kcl, pk);                          \
        }                                                                      \
    } while (0)

    ISSUE64(0, 0);
    CP_COMMIT();
    ISSUE64(KC, 1);
    CP_COMMIT();
    CP_WAIT1();
    __syncthreads();

    for (int t = 0; t < NKT; t++) {
        const uint32_t sS = smbase + (uint32_t)((t & 1) * BUFH64) * 2u;
        const int krem = K - t * KC;
#pragma unroll
        for (int ks = 0; ks < 4; ks++) {
            if (ks * 16 >= krem) break;
            const uint32_t kof = (uint32_t)(ks * 32);
            uint32_t bf[4][2];
#pragma unroll
            for (int jj = 0; jj < 2; jj++)
                ldsm_x4(bf[2 * jj][0], bf[2 * jj][1],
                        bf[2 * jj + 1][0], bf[2 * jj + 1][1], sS + offB[jj] + kof);
            uint32_t af0[4], af1[4];
            ldsm_x4(af0[0], af0[1], af0[2], af0[3], sS + offA0 + kof);
            ldsm_x4(af1[0], af1[1], af1[2], af1[3], sS + offA1 + kof);
#pragma unroll
            for (int j = 0; j < 4; j++) {
                mma_f16(d[0][j], af0, bf[j]);
                mma_f16(d[1][j], af1, bf[j]);
            }
        }
        __syncthreads();
        if (t + 2 < NKT) { ISSUE64((t + 2) * KC, t & 1); CP_COMMIT(); }
        if (t + 1 < NKT) {
            if (t + 2 < NKT) CP_WAIT1(); else CP_WAIT0();
            __syncthreads();
        }
    }

#pragma unroll
    for (int i = 0; i < 2; i++) {
        int mr[2];
        mr[0] = m_base + wm * 32 + i * 16 + g;
        mr[1] = mr[0] + 8;
#pragma unroll
        for (int j = 0; j < 4; j++) {
            int n0 = n_base + wn * 32 + j * 8 + tq * 2;
#pragma unroll
            for (int rr = 0; rr < 2; rr++) {
                float v0 = d[i][j][rr * 2 + 0];
                float v1 = d[i][j][rr * 2 + 1];
                int m = mr[rr];
                float4 q = *(const float4*)(rs + m * RNUM);
                float c0 = q.x * b2[n0]            + q.y * b2[DIMN + n0]
                         + q.z * b2[2 * DIMN + n0] + q.w * b2[3 * DIMN + n0];
                float c1 = q.x * b2[n0 + 1]            + q.y * b2[DIMN + n0 + 1]
                         + q.z * b2[2 * DIMN + n0 + 1] + q.w * b2[3 * DIMN + n0 + 1];
                *(float2*)(out + (size_t)m * DIMN + n0) =
                    make_float2(v0 + c0, v1 + c1);
            }
        }
    }

    if (blockIdx.x == 0) {
        int idx = blockIdx.y * 512 + tid * 2;
        *(float2*)(out + (size_t)TOK * DIMN + idx) = *(const float2*)(rs + idx);
    }
#undef ISSUE64
}

// ============================================================
// Flash attention (R13: ldmatrix + ex2, occupancy 3).
// ============================================================
#define LDQH 24
#define LDPH 136
#define FA_SMEM ((128 * LDQH * 2 + 16 * LDPH + 128 * LDPH) * 2)
#define QK_SCALE 0.360673760222241f

__global__ void __launch_bounds__(256, 3) fa_kernel()
{
    extern __shared__ __half fsh[];
    __half* Qs = fsh;
    __half* Ks = fsh + 128 * LDQH;
    __half* Vs = fsh + 2 * 128 * LDQH;
    __half* Ps = Vs + 16 * LDPH;
    const uint32_t uQs = smem_u32(Qs);
    const uint32_t uKs = smem_u32(Ks);
    const uint32_t uVs = smem_u32(Vs);
    const uint32_t uPs = smem_u32(Ps);

    const int qt = blockIdx.x;
    const int gg = blockIdx.y;
    const int bb = blockIdx.z;
    const int r = gg >> 3, hh = gg & 7;
    const int tid = threadIdx.x;
    const int wid = tid >> 5, lane = tid & 31;
    const int g = lane >> 2, tq = lane & 3;
    const int l8 = lane & 7, lm = lane >> 3;

    const __half* gq = g_qkv;
    const __half* gk = g_qkv + (size_t)TOK * DIMN;
    const __half* gv = g_qkv + 2 * (size_t)TOK * DIMN;
    const int seq0 = bb * NSEQ;

    const __half2 qscale = __floats2half2_rn(QK_SCALE, QK_SCALE);

    {
        int row = tid >> 1, part = tid & 1;
        int tok = seq0 + qt * 128 + row;
        uint4 v = *(const uint4*)(gq + (size_t)tok * DIMN + gg * HD + part * 8);
        __half2* pv = (__half2*)&v;
#pragma unroll
        for (int l = 0; l < 4; l++) pv[l] = __hmul2(pv[l], qscale);
        *(uint4*)(Qs + row * LDQH + part * 8) = v;
    }

    float o[2][4];
#pragma unroll
    for (int j = 0; j < 2; j++)
#pragma unroll
        for (int c = 0; c < 4; c++) o[j][c] = 0.f;
    float lsum[2] = {0.f, 0.f};

    const int row0 = wid * 16 + g;

    const uint32_t offQA = (uint32_t)(((wid * 16 + (lm & 1) * 8 + l8) * LDQH
                                       + (lm >> 1) * 8) * 2);
    uint32_t offKB[4];
#pragma unroll
    for (int jj = 0; jj < 4; jj++)
        offKB[jj] = (uint32_t)(((jj * 16 + (lm >> 1) * 8 + l8) * LDQH
                                + (lm & 1) * 8) * 2);
    const uint32_t offPA = (uint32_t)(((wid * 16 + (lm & 1) * 8 + l8) * LDPH
                                       + (lm >> 1) * 8) * 2);
    const uint32_t offVB = (uint32_t)((((lm >> 1) * 8 + l8) * LDPH
                                       + (lm & 1) * 8) * 2);

    for (int jt = 0; jt < 4; jt++) {
        {
            int row = tid >> 1, part = tid & 1;
            int tok = seq0 + jt * 128 + row;
            uint4 kv = *(const uint4*)(gk + (size_t)tok * DIMN + gg * HD + part * 8);
            *(uint4*)(Ks + row * LDQH + part * 8) = kv;
            uint4 vv = *(const uint4*)(gv + (size_t)tok * DIMN + gg * HD + part * 8);
            __half tmp[8];
            *(uint4*)tmp = vv;
            int d0 = part * 8;
#pragma unroll
            for (int l = 0; l < 8; l++) Vs[(d0 + l) * LDPH + row] = tmp[l];
        }
        __syncthreads();

        uint32_t af[4];
        ldsm_x4(af[0], af[1], af[2], af[3], uQs + offQA);

#pragma unroll
        for (int hn = 0; hn < 2; hn++) {
            const uint32_t hof = (uint32_t)(hn * 64 * LDQH * 2);
            uint32_t bf[8][2];
#pragma unroll
            for (int jj = 0; jj < 4; jj++)
                ldsm_x4(bf[2 * jj][0], bf[2 * jj][1],
                        bf[2 * jj + 1][0], bf[2 * jj + 1][1],
                        uKs + offKB[jj] + hof);
            float s[8][4];
#pragma unroll
            for (int jn = 0; jn < 8; jn++) {
#pragma unroll
                for (int c = 0; c < 4; c++) s[jn][c] = 0.f;
                mma_f16(s[jn], af, bf[jn]);
            }
#pragma unroll
            for (int jn = 0; jn < 8; jn++) {
                int c0 = hn * 64 + jn * 8 + 2 * tq;
                int gc0 = jt * 128 + c0;
#pragma unroll
                for (int rr = 0; rr < 2; rr++) {
                    int rl = row0 + rr * 8;
                    int grow = qt * 128 + rl;
                    float p0 = ex2(s[jn][rr * 2 + 0]);
                    float p1 = ex2(s[jn][rr * 2 + 1]);
                    if (gc0 == grow)     p0 = 0.f;
                    if (gc0 + 1 == grow) p1 = 0.f;
                    lsum[rr] += p0 + p1;
                    *(__half2*)(Ps + rl * LDPH + c0) = __floats2half2_rn(p0, p1);
                }
            }
        }
        __syncthreads();

#pragma unroll
        for (int ksi = 0; ksi < 8; ksi++) {
            const uint32_t kof = (uint32_t)(ksi * 32);
            uint32_t pa[4];
            ldsm_x4(pa[0], pa[1], pa[2], pa[3], uPs + offPA + kof);
            uint32_t bf[2][2];
            ldsm_x4(bf[0][0], bf[0][1], bf[1][0], bf[1][1], uVs + offVB + kof);
            mma_f16(o[0], pa, bf[0]);
            mma_f16(o[1], pa, bf[1]);
        }
        __syncthreads();
    }

#pragma unroll
    for (int rr = 0; rr < 2; rr++) {
        lsum[rr] += __shfl_xor_sync(0xFFFFFFFF, lsum[rr], 1);
        lsum[rr] += __shfl_xor_sync(0xFFFFFFFF, lsum[rr], 2);
    }
    float inv[2] = {1.f / lsum[0], 1.f / lsum[1]};

#pragma unroll
    for (int rr = 0; rr < 2; rr++) {
        int tok = seq0 + qt * 128 + row0 + rr * 8;
        __half* dst = g_h1 + (size_t)tok * H1LD + r * DIN1 + hh * HD;
#pragma unroll
        for (int jn = 0; jn < 2; jn++) {
            int col = jn * 8 + 2 * tq;
            *(__half2*)(dst + col) = __floats2half2_rn(o[jn][rr * 2 + 0] * inv[rr],
                                                       o[jn][rr * 2 + 1] * inv[rr]);
        }
    }
}

// ============================================================
extern "C" void kernel_launch(void* const* d_in, const int* in_sizes, int n_in,
                              void* d_out, int out_size)
{
    const float* x    = (const float*)d_in[0];
    const float* rs   = (const float*)d_in[1];
    const float* Wq   = (const float*)d_in[2];
    const float* bq   = (const float*)d_in[3];
    const float* Wk   = (const float*)d_in[4];
    const float* bk   = (const float*)d_in[5];
    const float* Wv   = (const float*)d_in[6];
    const float* bv   = (const float*)d_in[7];
    const float* Win  = (const float*)d_in[8];
    const float* b_in = (const float*)d_in[9];
    const float* W1   = (const float*)d_in[10];
    const float* b1   = (const float*)d_in[11];
    const float* W2   = (const float*)d_in[12];
    const float* b2   = (const float*)d_in[13];
    float* out = (float*)d_out;

    cudaFuncSetAttribute(mma_gemm<0>, cudaFuncAttributeMaxDynamicSharedMemorySize, GEMM_SMEM);
    cudaFuncSetAttribute(mma_gemm<2>, cudaFuncAttributeMaxDynamicSharedMemorySize, GEMM_SMEM);
    cudaFuncSetAttribute(mma_gemm64, cudaFuncAttributeMaxDynamicSharedMemorySize, GEMM64_SMEM);
    cudaFuncSetAttribute(fa_kernel, cudaFuncAttributeMaxDynamicSharedMemorySize, FA_SMEM);

    conv_all<<<2132, 256>>>(x, Wq, Wk, Wv, Win, W1, W2);

    mma_gemm<0><<<dim3(4, 32, 4), 256, GEMM_SMEM>>>(bq, bk, bv, b_in, b1, rs);
    fa_kernel<<<dim3(4, GQ, 8), 256, FA_SMEM>>>();
    mma_gemm<2><<<dim3(4, 32, 4), 256, GEMM_SMEM>>>(bq, bk, bv, b_in, b1, rs);
    mma_gemm64<<<dim3(8, 32), 256, GEMM64_SMEM>>>(b2, rs, out);
}